// round 10
// baseline (speedup 1.0000x reference)
#include <cuda_runtime.h>
#include <cuda_bf16.h>

// Inverse db1 DWT (Haar), grouped transposed conv 2x2 stride 2 — no overlap.
// x: (16, 128, 128, 128) f32; inv_filters: (2,2,2) f32
// out: (16, 64, 256, 256) f32
//
// out[b,g,2h+i,2w+j] = x[b,2g,h,w]*f0[i,j] + x[b,2g+1,h,w]*f1[i,j]
//
// R9: 4 pixel-pairs per thread = (2 w-chunks at lane-distance 32) x
// (2 h-rows at distance 64). Every load is float2 with warp stride 8 B
// (256 B dense); every store is float4 with warp stride 16 B (512 B dense).
// MLP = 8 loads in flight per thread to deepen DRAM command queues.

static constexpr int B    = 16;
static constexpr int G    = 64;    // C/2 groups
static constexpr int H    = 128;
static constexpr int W    = 128;
static constexpr int HALF = 32;    // half of the 64 pixel-pairs per row
static constexpr int H2   = 64;    // half of H
static constexpr long long TOTAL = (long long)B * G * H2 * HALF;  // 2,097,152

__device__ __forceinline__ float4 mix4(float2 lo, float2 hi,
                                       float fa, float fb, float ga, float gb)
{
    float4 r;
    r.x = fmaf(hi.x, ga, lo.x * fa);
    r.y = fmaf(hi.x, gb, lo.x * fb);
    r.z = fmaf(hi.y, ga, lo.y * fa);
    r.w = fmaf(hi.y, gb, lo.y * fb);
    return r;
}

__global__ __launch_bounds__(256)
void iwt_kernel(const float2* __restrict__ x,
                const float*  __restrict__ f,
                float4* __restrict__ out)
{
    int idx = blockIdx.x * blockDim.x + threadIdx.x;   // < 2^21
    int w2 = idx & (HALF - 1);          // 0..31  (lane-aligned)
    int h0 = (idx >> 5) & (H2 - 1);     // 0..63 ; rows h0 and h0+64
    int bg = idx >> 11;                 // b*G + g, 0..1023

    // input in float2 units: channel plane = H*W/2 = 8192, row = 64
    const int IROW   = W / 2;           // 64
    const int IPLANE = H * W / 2;       // 8192
    int ib = (2 * bg) * IPLANE + h0 * IROW + w2;
    int dh = H2 * IROW;                 // row h0+64 offset = 4096

    float2 lo00 = __ldcs(x + ib);
    float2 lo01 = __ldcs(x + ib + HALF);
    float2 lo10 = __ldcs(x + ib + dh);
    float2 lo11 = __ldcs(x + ib + dh + HALF);
    float2 hi00 = __ldcs(x + ib + IPLANE);
    float2 hi01 = __ldcs(x + ib + IPLANE + HALF);
    float2 hi10 = __ldcs(x + ib + IPLANE + dh);
    float2 hi11 = __ldcs(x + ib + IPLANE + dh + HALF);

    // filters: f[0..3] = f0 row-major, f[4..7] = f1 row-major
    float f00 = __ldg(f + 0), f01 = __ldg(f + 1);
    float f02 = __ldg(f + 2), f03 = __ldg(f + 3);
    float g00 = __ldg(f + 4), g01 = __ldg(f + 5);
    float g02 = __ldg(f + 6), g03 = __ldg(f + 7);

    // output in float4 units: plane per (b,g) = 256*256/4 = 16384, row = 64
    const int OROW   = 2 * W / 4;       // 64
    const int OPLANE = 2 * H * 2 * W / 4;  // 16384
    int ob  = bg * OPLANE + (2 * h0) * OROW + w2;
    int odh = 2 * H2 * OROW;            // output rows for h0+64 start here (8192)

    // h0, row 2h0
    __stcs(out + ob,               mix4(lo00, hi00, f00, f01, g00, g01));
    __stcs(out + ob + HALF,        mix4(lo01, hi01, f00, f01, g00, g01));
    // h0, row 2h0+1
    __stcs(out + ob + OROW,        mix4(lo00, hi00, f02, f03, g02, g03));
    __stcs(out + ob + OROW + HALF, mix4(lo01, hi01, f02, f03, g02, g03));
    // h0+64, row 2(h0+64)
    __stcs(out + ob + odh,               mix4(lo10, hi10, f00, f01, g00, g01));
    __stcs(out + ob + odh + HALF,        mix4(lo11, hi11, f00, f01, g00, g01));
    // h0+64, row 2(h0+64)+1
    __stcs(out + ob + odh + OROW,        mix4(lo10, hi10, f02, f03, g02, g03));
    __stcs(out + ob + odh + OROW + HALF, mix4(lo11, hi11, f02, f03, g02, g03));
}

extern "C" void kernel_launch(void* const* d_in, const int* in_sizes, int n_in,
                              void* d_out, int out_size)
{
    const float2* x = (const float2*)d_in[0];
    const float*  f = (const float*)d_in[1];
    float4* out     = (float4*)d_out;

    const int threads = 256;
    const int blocks  = (int)(TOTAL / threads);   // 8192, exact
    iwt_kernel<<<blocks, threads>>>(x, f, out);
}